// round 11
// baseline (speedup 1.0000x reference)
#include <cuda_runtime.h>
#include <math.h>

// mParametricLIF: x [N=128, T=64, D=4096] f32 -> spikes [N,T,D] f32.
//   m = lam*m + k*(x - v);  v += m;  s = (v >= th);  v = s ? 0 : v;  out = s
// k = sigmoid(tau_param[0]), lam = lamb[0], th = th[0].
//
// R11 = R10 theory with the ptxas-legal encoding: sm_100 rejects the inline
// .L2::evict_last modifier at .v4.f32 width; use createpolicy.fractional +
// ld.global.nc.L2::cache_hint.v4.f32 (policy register form) instead.
//  - pin a STATIC 100MB prefix of x (n < PERSIST_N) as L2 evict_last; the
//    cyclic re-read across graph replays thrashes LRU unless a fixed subset
//    is priority-pinned.
//  - remainder of x loaded __ldcs, output stored __stcs (evict-first) so
//    streaming traffic cannot displace the pinned set.
//  - otherwise exact R2 structure: float4 lanes, batched 8-deep loads,
//    block=128, grid=1024.

#define TU 8
#define BT 128
#define PERSIST_N 100   // n < 100 -> 100MB of x pinned in 126MB L2

__device__ __forceinline__ float4 ldg_evict_last(const float4* p,
                                                 unsigned long long pol) {
    float4 r;
    asm volatile("ld.global.nc.L2::cache_hint.v4.f32 {%0,%1,%2,%3}, [%4], %5;"
                 : "=f"(r.x), "=f"(r.y), "=f"(r.z), "=f"(r.w)
                 : "l"(p), "l"(pol));
    return r;
}

__device__ __forceinline__ void lif_step(float4 xv, float4& v, float4& m,
                                         float k, float lam, float th,
                                         float4& s)
{
    m.x = lam * m.x + k * (xv.x - v.x); v.x += m.x;
    m.y = lam * m.y + k * (xv.y - v.y); v.y += m.y;
    m.z = lam * m.z + k * (xv.z - v.z); v.z += m.z;
    m.w = lam * m.w + k * (xv.w - v.w); v.w += m.w;

    s.x = (v.x >= th) ? 1.0f : 0.0f;
    s.y = (v.y >= th) ? 1.0f : 0.0f;
    s.z = (v.z >= th) ? 1.0f : 0.0f;
    s.w = (v.w >= th) ? 1.0f : 0.0f;

    v.x = (s.x != 0.0f) ? 0.0f : v.x;
    v.y = (s.y != 0.0f) ? 0.0f : v.y;
    v.z = (s.z != 0.0f) ? 0.0f : v.z;
    v.w = (s.w != 0.0f) ? 0.0f : v.w;
}

__global__ __launch_bounds__(BT) void mplif_kernel(
    const float4* __restrict__ x4,
    const float* __restrict__ tau_param,
    const float* __restrict__ lamb,
    const float* __restrict__ thr,
    float4* __restrict__ out4,
    int T, int DC /* D/4 */)
{
    int tid = blockIdx.x * BT + threadIdx.x;
    int n = tid / DC;
    int c = tid - n * DC;
    long base = (long)n * T * DC + c;

    const float k   = 1.0f / (1.0f + expf(-tau_param[0]));
    const float lam = lamb[0];
    const float th  = thr[0];

    float4 v = make_float4(0.f, 0.f, 0.f, 0.f);
    float4 m = make_float4(0.f, 0.f, 0.f, 0.f);

    float4 buf[TU];
    const bool persist = (n < PERSIST_N);   // block-uniform (8 blocks per n)

    // evict_last policy for the pinned fraction (100% of hinted accesses).
    unsigned long long pol;
    asm volatile("createpolicy.fractional.L2::evict_last.b64 %0, 1.0;"
                 : "=l"(pol));

    for (int t0 = 0; t0 < T; t0 += TU) {
        // Batch independent loads first (MLP = TU LDG.128).
        if (persist) {
            #pragma unroll
            for (int j = 0; j < TU; j++)
                buf[j] = ldg_evict_last(&x4[base + (long)(t0 + j) * DC], pol);
        } else {
            #pragma unroll
            for (int j = 0; j < TU; j++)
                buf[j] = __ldcs(&x4[base + (long)(t0 + j) * DC]);
        }
        // Serial recurrence on registers.
        #pragma unroll
        for (int j = 0; j < TU; j++) {
            float4 s;
            lif_step(buf[j], v, m, k, lam, th, s);
            __stcs(&out4[base + (long)(t0 + j) * DC], s);
        }
    }
}

extern "C" void kernel_launch(void* const* d_in, const int* in_sizes, int n_in,
                              void* d_out, int out_size)
{
    const float* x         = (const float*)d_in[0];
    const float* tau_param = (const float*)d_in[1];
    const float* lamb      = (const float*)d_in[2];
    const float* th        = (const float*)d_in[3];
    float* out             = (float*)d_out;

    const int N = 128, T = 64, D = 4096;
    const int DC = D / 4;
    const int lanes = N * DC;

    dim3 block(BT);
    dim3 grid(lanes / BT);   // 1024 blocks, exact
    mplif_kernel<<<grid, block>>>((const float4*)x, tau_param, lamb, th,
                                  (float4*)out, T, DC);
}

// round 12
// speedup vs baseline: 1.0490x; 1.0490x over previous
#include <cuda_runtime.h>
#include <math.h>

// mParametricLIF: x [N=128, T=64, D=4096] f32 -> spikes [N,T,D] f32.
//   m = lam*m + k*(x - v);  v += m;  s = (v >= th);  v = s ? 0 : v;  out = s
// k = sigmoid(tau_param[0]), lam = lamb[0], th = th[0].
//
// R12: cp.async DOUBLE-BUFFERED BURST pipeline.
// Evidence: R2 (8-load/8-store bursts, sawtooth MLP) 40.5us beats R9
// (constant MLP, fully interleaved LDG/STG) 41.5us -> DRAM R/W turnaround
// matters. This kernel gets both properties:
//  - reads and writes hit DRAM in segregated 8-deep bursts (turnaround-
//    friendly), AND >=8 loads/thread in flight at ALL times (no sawtooth).
//  - in-flight data lives in smem (2 x 8 x 128 x 16B = 32KB/block,
//    7 blocks/SM = 224KB, exactly one wave of 1024 blocks), regs stay ~38.
//  - per-thread cp.async wait_group; zero block barriers.
//  - cp.async.cg bypasses L1; stores __stcs (write-once, evict-first).

#define S  8      // timesteps per burst / per buffer
#define BT 128    // threads per block

#define CP_ASYNC16(saddr, gptr)                                             \
    asm volatile("cp.async.cg.shared.global [%0], [%1], 16;\n"              \
                 :: "r"(saddr), "l"(gptr) : "memory")
#define CP_COMMIT()  asm volatile("cp.async.commit_group;\n" ::: "memory")
#define CP_WAIT(n)   asm volatile("cp.async.wait_group %0;\n" :: "n"(n) : "memory")

__device__ __forceinline__ void lif_step(float4 xv, float4& v, float4& m,
                                         float k, float lam, float th,
                                         float4& s)
{
    m.x = lam * m.x + k * (xv.x - v.x); v.x += m.x;
    m.y = lam * m.y + k * (xv.y - v.y); v.y += m.y;
    m.z = lam * m.z + k * (xv.z - v.z); v.z += m.z;
    m.w = lam * m.w + k * (xv.w - v.w); v.w += m.w;

    s.x = (v.x >= th) ? 1.0f : 0.0f;
    s.y = (v.y >= th) ? 1.0f : 0.0f;
    s.z = (v.z >= th) ? 1.0f : 0.0f;
    s.w = (v.w >= th) ? 1.0f : 0.0f;

    v.x = (s.x != 0.0f) ? 0.0f : v.x;
    v.y = (s.y != 0.0f) ? 0.0f : v.y;
    v.z = (s.z != 0.0f) ? 0.0f : v.z;
    v.w = (s.w != 0.0f) ? 0.0f : v.w;
}

__global__ __launch_bounds__(BT) void mplif_kernel(
    const float4* __restrict__ x4,
    const float* __restrict__ tau_param,
    const float* __restrict__ lamb,
    const float* __restrict__ thr,
    float4* __restrict__ out4,
    int T, int DC /* D/4 */)
{
    __shared__ float4 stage[2][S][BT];   // 32 KB, stage-major, conflict-free

    int tid = blockIdx.x * BT + threadIdx.x;   // lanes = 1024*128 exactly
    int n = tid / DC;
    int c = tid - n * DC;
    long base = (long)n * T * DC + c;

    const float k   = 1.0f / (1.0f + expf(-tau_param[0]));
    const float lam = lamb[0];
    const float th  = thr[0];

    const float4* __restrict__ px = x4 + base;    // prefetch cursor
    float4*       __restrict__ po = out4 + base;  // store cursor

    unsigned int s_tid = (unsigned int)__cvta_generic_to_shared(
                             &stage[0][0][threadIdx.x]);
    const unsigned int slot = BT * sizeof(float4);        // 2048 B per stage
    const unsigned int bufB = S * slot;                   // buffer stride

    float4 v = make_float4(0.f, 0.f, 0.f, 0.f);
    float4 m = make_float4(0.f, 0.f, 0.f, 0.f);

    // Prologue: two full load bursts (groups G0 -> buf0, G1 -> buf1).
    #pragma unroll
    for (int j = 0; j < S; j++) { CP_ASYNC16(s_tid + j * slot, px); px += DC; }
    CP_COMMIT();
    #pragma unroll
    for (int j = 0; j < S; j++) { CP_ASYNC16(s_tid + bufB + j * slot, px); px += DC; }
    CP_COMMIT();

    int cur = 0;
    // Steady state: iterations 0..T/S-3 refill; last two just drain.
    for (int t0 = 0; t0 < T - 2 * S; t0 += S) {
        CP_WAIT(1);                               // buffer `cur` ready
        // Compute + STORE BURST (8 STG.128 back-to-back).
        #pragma unroll
        for (int j = 0; j < S; j++) {
            float4 s;
            lif_step(stage[cur][j][threadIdx.x], v, m, k, lam, th, s);
            __stcs(po, s);
            po += DC;
        }
        // LOAD BURST refilling the buffer just consumed.
        unsigned int b = s_tid + (unsigned int)cur * bufB;
        #pragma unroll
        for (int j = 0; j < S; j++) { CP_ASYNC16(b + j * slot, px); px += DC; }
        CP_COMMIT();
        cur ^= 1;
    }

    // Drain: second-to-last buffer (one group still pending behind it).
    CP_WAIT(1);
    #pragma unroll
    for (int j = 0; j < S; j++) {
        float4 s;
        lif_step(stage[cur][j][threadIdx.x], v, m, k, lam, th, s);
        __stcs(po, s);
        po += DC;
    }
    cur ^= 1;

    // Drain: last buffer.
    CP_WAIT(0);
    #pragma unroll
    for (int j = 0; j < S; j++) {
        float4 s;
        lif_step(stage[cur][j][threadIdx.x], v, m, k, lam, th, s);
        __stcs(po, s);
        po += DC;
    }
}

extern "C" void kernel_launch(void* const* d_in, const int* in_sizes, int n_in,
                              void* d_out, int out_size)
{
    const float* x         = (const float*)d_in[0];
    const float* tau_param = (const float*)d_in[1];
    const float* lamb      = (const float*)d_in[2];
    const float* th        = (const float*)d_in[3];
    float* out             = (float*)d_out;

    const int N = 128, T = 64, D = 4096;
    const int DC = D / 4;
    const int lanes = N * DC;

    dim3 block(BT);
    dim3 grid(lanes / BT);   // 1024 blocks, exact
    mplif_kernel<<<grid, block>>>((const float4*)x, tau_param, lamb, th,
                                  (float4*)out, T, DC);
}